// round 12
// baseline (speedup 1.0000x reference)
#include <cuda_runtime.h>
#include <cuda_bf16.h>

// SpatialConsistencyLoss — single launch, producer/consumer block split.
//   original, enhanced: [32,3,512,512] f32
//   p = avg_pool4(mean_c(orig)) - avg_pool4(mean_c(enh))   [32,128,128]
//   loss[i,j] = sum_dirs (p[i,j] - p[nbr])^2, zero-padded  -> [32,1,128,128]
//
// Blocks 0..2047: EXACT copy of the proven 6.4 TB/s streaming pool body
//   (one pooled pixel/thread, 24 warp-contiguous __ldcs float4 loads), plus
//   one block-level threadfence + atomicAdd at the end. They retire
//   naturally — no residency constraint, no per-thread sync (R8's mistake).
// Blocks 2048..2559: consumer blocks (scheduled last in bid order). Thread 0
//   spins on the completion counter; then the block computes a 4-pixel-wide
//   float4 loss tile (the best standalone loss body). This deletes the
//   second kernel's ~4us launch/ramp/drain overhead, which PDL failed to
//   hide and every fused-stream variant paid for in stream bandwidth.
// Deadlock-free: 512 spinning blocks << ~1184-block chip capacity, so
// producers always find slots. Counters self-reset => graph-replay safe.

#define B 32
#define HP 128
#define WP 128
#define NPOOL (B * HP * WP)   // 524288
#define HIN 512
#define WIN 512
#define CH_STRIDE (HIN * WIN)          // 262144
#define IMG_STRIDE (3 * CH_STRIDE)     // 786432
#define THREADS 256
#define POOL_BLOCKS (NPOOL / THREADS)      // 2048
#define LOSS_BLOCKS (NPOOL / 4 / THREADS)  // 512

__device__ float g_pooled[NPOOL];      // 2 MB scratch
__device__ unsigned int g_done = 0;    // pool-block completion counter
__device__ unsigned int g_exit = 0;    // consumer exit counter (for reset)

__device__ __forceinline__ float sq(float x) { return x * x; }

__global__ void scl_prodcons_kernel(const float* __restrict__ orig,
                                    const float* __restrict__ enh,
                                    float* __restrict__ out) {
    if (blockIdx.x < POOL_BLOCKS) {
        // ================= Producer: streaming pool block =================
        int idx = blockIdx.x * THREADS + threadIdx.x;

        int j = idx & (WP - 1);
        int i = (idx >> 7) & (HP - 1);
        int b = idx >> 14;

        int base0 = b * IMG_STRIDE + (i * 4) * WIN + (j * 4);

        float s = 0.0f;
#pragma unroll
        for (int c = 0; c < 3; ++c) {
            int base = base0 + c * CH_STRIDE;
#pragma unroll
            for (int r = 0; r < 4; ++r) {
                float4 ov = __ldcs(reinterpret_cast<const float4*>(orig + base + r * WIN));
                float4 ev = __ldcs(reinterpret_cast<const float4*>(enh  + base + r * WIN));
                s += (ov.x - ev.x) + (ov.y - ev.y) + (ov.z - ev.z) + (ov.w - ev.w);
            }
        }
        g_pooled[idx] = s * (1.0f / 48.0f);   // /3 channels, /16 pool

        __syncthreads();
        if (threadIdx.x == 0) {
            __threadfence();                  // release this block's scratch rows
            atomicAdd(&g_done, 1u);
        }
        // Block retires; SM slot freed for remaining stream.
    } else {
        // ================= Consumer: loss block ===========================
        // Scheduled after all producers (bid order); spins only during the
        // stream tail. One polling thread per block, ~300cyc poll interval.
        if (threadIdx.x == 0) {
            while (*(volatile unsigned int*)&g_done < POOL_BLOCKS) { }
            __threadfence();                  // acquire producers' stores
        }
        __syncthreads();

        int t = (blockIdx.x - POOL_BLOCKS) * THREADS + threadIdx.x;

        int j4  = (t & 31) << 2;      // first j of the 4-wide quad
        int row = t >> 5;             // b*128 + i
        int i   = row & (HP - 1);
        int base = (row << 7) + j4;

        const float4* p4 = reinterpret_cast<const float4*>(g_pooled);
        float4 c  = p4[base >> 2];
        float4 up = (i > 0)      ? p4[(base - WP) >> 2] : make_float4(0.f, 0.f, 0.f, 0.f);
        float4 dn = (i < HP - 1) ? p4[(base + WP) >> 2] : make_float4(0.f, 0.f, 0.f, 0.f);
        float left  = (j4 > 0)      ? g_pooled[base - 1] : 0.f;
        float right = (j4 < WP - 4) ? g_pooled[base + 4] : 0.f;

        float4 o;
        o.x = sq(c.x - left) + sq(c.x - c.y)   + sq(c.x - up.x) + sq(c.x - dn.x);
        o.y = sq(c.y - c.x)  + sq(c.y - c.z)   + sq(c.y - up.y) + sq(c.y - dn.y);
        o.z = sq(c.z - c.y)  + sq(c.z - c.w)   + sq(c.z - up.z) + sq(c.z - dn.z);
        o.w = sq(c.w - c.z)  + sq(c.w - right) + sq(c.w - up.w) + sq(c.w - dn.w);

        reinterpret_cast<float4*>(out)[base >> 2] = o;

        // -------- Reset counters for the next graph replay --------
        __syncthreads();
        if (threadIdx.x == 0) {
            unsigned int old = atomicAdd(&g_exit, 1u);
            if (old == LOSS_BLOCKS - 1) {     // last consumer out resets both
                atomicExch(&g_done, 0u);
                atomicExch(&g_exit, 0u);
            }
        }
    }
}

extern "C" void kernel_launch(void* const* d_in, const int* in_sizes, int n_in,
                              void* d_out, int out_size) {
    const float* orig = (const float*)d_in[0];
    const float* enh  = (const float*)d_in[1];
    float* out = (float*)d_out;

    scl_prodcons_kernel<<<POOL_BLOCKS + LOSS_BLOCKS, THREADS>>>(orig, enh, out);
}